// round 3
// baseline (speedup 1.0000x reference)
#include <cuda_runtime.h>
#include <math.h>

#define HID 4096
#define INT_DIM 16384
#define MTOK 8192
#define LN_EPS 1e-5f

// Scratch (allocation-free rule: __device__ globals)
__device__ float g_res[(size_t)MTOK * HID];       // 128 MB
__device__ float g_ln[(size_t)MTOK * HID];        // 128 MB (tf32-rounded)
__device__ float g_inter[(size_t)MTOK * INT_DIM]; // 512 MB

__device__ __forceinline__ float to_tf32(float x) {
    unsigned u;
    asm("cvt.rna.tf32.f32 %0, %1;" : "=r"(u) : "f"(x));
    return __uint_as_float(u);
}

__device__ __forceinline__ float gelu_tanh(float x) {
    float x3 = x * x * x;
    return 0.5f * x * (1.0f + tanhf(0.7978845608028654f * (x + 0.044715f * x3)));
}

// ---------------------------------------------------------------------------
// Kernel 1: res = input + residual + bias; ln = LN(res)*gamma + beta
// One block per token row, 256 threads, 16 elems/thread.
// ---------------------------------------------------------------------------
__global__ __launch_bounds__(256) void addln_kernel(
    const float* __restrict__ x, const float* __restrict__ r,
    const float* __restrict__ bias, const float* __restrict__ gamma,
    const float* __restrict__ beta)
{
    const int row = blockIdx.x;
    const int tid = threadIdx.x;
    const size_t base = (size_t)row * HID;

    float v[16];
    float sum = 0.f, sq = 0.f;
#pragma unroll
    for (int i = 0; i < 16; i++) {
        const int idx = tid + i * 256;
        const float t = x[base + idx] + r[base + idx] + bias[idx];
        v[i] = t;
        sum += t;
        sq += t * t;
    }
    __shared__ float s1[8], s2[8];
#pragma unroll
    for (int o = 16; o > 0; o >>= 1) {
        sum += __shfl_xor_sync(0xffffffffu, sum, o);
        sq  += __shfl_xor_sync(0xffffffffu, sq, o);
    }
    if ((tid & 31) == 0) { s1[tid >> 5] = sum; s2[tid >> 5] = sq; }
    __syncthreads();
    float fs = 0.f, fq = 0.f;
#pragma unroll
    for (int i = 0; i < 8; i++) { fs += s1[i]; fq += s2[i]; }
    const float mu   = fs * (1.0f / HID);
    const float var  = fq * (1.0f / HID) - mu * mu;
    const float rstd = rsqrtf(var + LN_EPS);
#pragma unroll
    for (int i = 0; i < 16; i++) {
        const int idx = tid + i * 256;
        g_res[base + idx] = v[i];
        g_ln[base + idx]  = to_tf32((v[i] - mu) * rstd * gamma[idx] + beta[idx]);
    }
}

// ---------------------------------------------------------------------------
// TF32 mma.sync GEMM: C[M,N] = A[M,K] @ B[K,N] + epilogue
//   EPI==0: C = gelu(acc + bias[n])                 (-> g_inter)
//   EPI==1: C = acc + resid[m,n] + bias[n]          (-> d_out)
// Block tile 128x128x16, 8 warps (2x4), warp tile 64x32, double-buffered smem.
// ---------------------------------------------------------------------------
template <int EPI>
__global__ __launch_bounds__(256) void gemm_tf32(
    const float* __restrict__ A, const float* __restrict__ B,
    const float* __restrict__ bias, const float* __restrict__ resid,
    float* __restrict__ C, int N, int K)
{
    constexpr int BM = 128, BN = 128, BK = 16, ST = 20; // ST=20: conflict-free frag loads
    __shared__ float As[2][BM * ST];
    __shared__ float Bs[2][BN * ST];

    const int tid  = threadIdx.x;
    const int lane = tid & 31;
    const int warp = tid >> 5;
    const int g = lane >> 2;   // groupID
    const int t = lane & 3;    // threadID_in_group
    const int wm = (warp >> 2) * 64;
    const int wn = (warp & 3) * 32;
    const int m0 = blockIdx.y * BM;
    const int n0 = blockIdx.x * BN;

    // A loader: rows a_row, a_row+64; cols a_col..a_col+3
    const int a_row = tid >> 2;
    const int a_col = (tid & 3) * 4;
    // B loader: k = b_k; cols b_col..+3 and +64 (conflict-free transposed STS)
    const int b_k   = tid & 15;
    const int b_col = (tid >> 4) * 4;

    const float* Abase = A + (size_t)(m0 + a_row) * K + a_col;
    const float* Bbase = B + (size_t)b_k * N + n0 + b_col;

    float acc[4][4][4];
#pragma unroll
    for (int i = 0; i < 4; i++)
#pragma unroll
        for (int j = 0; j < 4; j++)
#pragma unroll
            for (int k = 0; k < 4; k++) acc[i][j][k] = 0.f;

    float4 ar[2], br[2];
    const int KT = K / BK;

#define STORE_TILE(bufi) do {                                                  \
        float* da = &As[bufi][a_row * ST + a_col];                             \
        da[0] = to_tf32(ar[0].x); da[1] = to_tf32(ar[0].y);                    \
        da[2] = to_tf32(ar[0].z); da[3] = to_tf32(ar[0].w);                    \
        float* da2 = &As[bufi][(a_row + 64) * ST + a_col];                     \
        da2[0] = to_tf32(ar[1].x); da2[1] = to_tf32(ar[1].y);                  \
        da2[2] = to_tf32(ar[1].z); da2[3] = to_tf32(ar[1].w);                  \
        float* db = &Bs[bufi][0];                                              \
        db[(b_col + 0) * ST + b_k] = to_tf32(br[0].x);                         \
        db[(b_col + 1) * ST + b_k] = to_tf32(br[0].y);                         \
        db[(b_col + 2) * ST + b_k] = to_tf32(br[0].z);                         \
        db[(b_col + 3) * ST + b_k] = to_tf32(br[0].w);                         \
        db[(b_col + 64 + 0) * ST + b_k] = to_tf32(br[1].x);                    \
        db[(b_col + 64 + 1) * ST + b_k] = to_tf32(br[1].y);                    \
        db[(b_col + 64 + 2) * ST + b_k] = to_tf32(br[1].z);                    \
        db[(b_col + 64 + 3) * ST + b_k] = to_tf32(br[1].w);                    \
    } while (0)

    // Prologue: tile 0
    ar[0] = *(const float4*)(Abase);
    ar[1] = *(const float4*)(Abase + (size_t)64 * K);
    br[0] = *(const float4*)(Bbase);
    br[1] = *(const float4*)(Bbase + 64);
    STORE_TILE(0);
    __syncthreads();

    for (int kt = 0; kt < KT; kt++) {
        const int buf = kt & 1;
        if (kt + 1 < KT) {
            const size_t ko = (size_t)(kt + 1) * BK;
            ar[0] = *(const float4*)(Abase + ko);
            ar[1] = *(const float4*)(Abase + (size_t)64 * K + ko);
            br[0] = *(const float4*)(Bbase + ko * N);
            br[1] = *(const float4*)(Bbase + ko * N + 64);
        }
        const float* as = As[buf];
        const float* bs = Bs[buf];
#pragma unroll
        for (int ks = 0; ks < 2; ks++) {
            unsigned af[4][4], bf[4][2];
#pragma unroll
            for (int mt = 0; mt < 4; mt++) {
                const int rb = wm + mt * 16;
                af[mt][0] = __float_as_uint(as[(rb + g)     * ST + ks * 8 + t]);
                af[mt][1] = __float_as_uint(as[(rb + g + 8) * ST + ks * 8 + t]);
                af[mt][2] = __float_as_uint(as[(rb + g)     * ST + ks * 8 + t + 4]);
                af[mt][3] = __float_as_uint(as[(rb + g + 8) * ST + ks * 8 + t + 4]);
            }
#pragma unroll
            for (int nt = 0; nt < 4; nt++) {
                const int nb = wn + nt * 8;
                bf[nt][0] = __float_as_uint(bs[(nb + g) * ST + ks * 8 + t]);
                bf[nt][1] = __float_as_uint(bs[(nb + g) * ST + ks * 8 + t + 4]);
            }
#pragma unroll
            for (int mt = 0; mt < 4; mt++)
#pragma unroll
                for (int nt = 0; nt < 4; nt++) {
                    asm volatile(
                        "mma.sync.aligned.m16n8k8.row.col.f32.tf32.tf32.f32 "
                        "{%0,%1,%2,%3},{%4,%5,%6,%7},{%8,%9},{%0,%1,%2,%3};"
                        : "+f"(acc[mt][nt][0]), "+f"(acc[mt][nt][1]),
                          "+f"(acc[mt][nt][2]), "+f"(acc[mt][nt][3])
                        : "r"(af[mt][0]), "r"(af[mt][1]),
                          "r"(af[mt][2]), "r"(af[mt][3]),
                          "r"(bf[nt][0]), "r"(bf[nt][1]));
                }
        }
        if (kt + 1 < KT) {
            STORE_TILE(buf ^ 1);
            __syncthreads();
        }
    }
#undef STORE_TILE

    // Epilogue
#pragma unroll
    for (int mt = 0; mt < 4; mt++) {
#pragma unroll
        for (int nt = 0; nt < 4; nt++) {
            const int col = n0 + wn + nt * 8 + 2 * t;
#pragma unroll
            for (int h = 0; h < 2; h++) {
                const int row = m0 + wm + mt * 16 + g + h * 8;
                const size_t off = (size_t)row * N + col;
                float2 v;
                v.x = acc[mt][nt][h * 2 + 0];
                v.y = acc[mt][nt][h * 2 + 1];
                if (EPI == 0) {
                    v.x = gelu_tanh(v.x + bias[col]);
                    v.y = gelu_tanh(v.y + bias[col + 1]);
                } else {
                    v.x += resid[off]     + bias[col];
                    v.y += resid[off + 1] + bias[col + 1];
                }
                *(float2*)(C + off) = v;
            }
        }
    }
}

// ---------------------------------------------------------------------------
// Launch
// ---------------------------------------------------------------------------
extern "C" void kernel_launch(void* const* d_in, const int* in_sizes, int n_in,
                              void* d_out, int out_size)
{
    const float* input     = (const float*)d_in[0];
    const float* residual  = (const float*)d_in[1];
    // d_in[2] = residual_norm: unused by the reference
    const float* attn_bias = (const float*)d_in[3];
    const float* attn_nw   = (const float*)d_in[4];
    const float* attn_nb   = (const float*)d_in[5];
    const float* inter_w   = (const float*)d_in[6];
    const float* inter_b   = (const float*)d_in[7];
    const float* output_w  = (const float*)d_in[8];
    const float* output_b  = (const float*)d_in[9];
    float* out = (float*)d_out;

    float *ln_p = nullptr, *res_p = nullptr, *inter_p = nullptr;
    cudaGetSymbolAddress((void**)&ln_p, g_ln);
    cudaGetSymbolAddress((void**)&res_p, g_res);
    cudaGetSymbolAddress((void**)&inter_p, g_inter);

    addln_kernel<<<MTOK, 256>>>(input, residual, attn_bias, attn_nw, attn_nb);

    gemm_tf32<0><<<dim3(INT_DIM / 128, MTOK / 128), 256>>>(
        ln_p, inter_w, inter_b, nullptr, inter_p, INT_DIM, HID);

    gemm_tf32<1><<<dim3(HID / 128, MTOK / 128), 256>>>(
        inter_p, output_w, output_b, res_p, out, HID, INT_DIM);
}

// round 6
// speedup vs baseline: 2.2592x; 2.2592x over previous
#include <cuda_runtime.h>
#include <math.h>
#include <stdint.h>

#define HID 4096
#define INT_DIM 16384
#define MTOK 8192
#define LN_EPS 1e-5f

// ---------------------------------------------------------------------------
// Scratch (__device__ globals: allocation-free rule)
// ---------------------------------------------------------------------------
__device__ float g_res[(size_t)MTOK * HID];        // 128 MB
__device__ float g_ln[(size_t)MTOK * HID];         // 128 MB (tf32 RNA)
__device__ float g_inter[(size_t)MTOK * INT_DIM];  // 512 MB (tf32 RNA)
__device__ float g_w1t[(size_t)INT_DIM * HID];     // 256 MB  W1^T, tf32 RNA
__device__ float g_w2t[(size_t)HID * INT_DIM];     // 256 MB  W2^T, tf32 RNA

__device__ __forceinline__ float to_tf32(float x) {
    unsigned u;
    asm("cvt.rna.tf32.f32 %0, %1;" : "=r"(u) : "f"(x));
    return __uint_as_float(u);
}

__device__ __forceinline__ float gelu_tanh(float x) {
    float x3 = x * x * x;
    return 0.5f * x * (1.0f + tanhf(0.7978845608028654f * (x + 0.044715f * x3)));
}

__device__ __forceinline__ void cp16(unsigned dst, const void* src) {
    asm volatile("cp.async.cg.shared.global [%0], [%1], 16;" :: "r"(dst), "l"(src) : "memory");
}

// ---------------------------------------------------------------------------
// Kernel 1: res = input + residual + bias; ln = tf32(LN(res)*gamma + beta)
// ---------------------------------------------------------------------------
__global__ __launch_bounds__(256) void addln_kernel(
    const float* __restrict__ x, const float* __restrict__ r,
    const float* __restrict__ bias, const float* __restrict__ gamma,
    const float* __restrict__ beta)
{
    const int row = blockIdx.x;
    const int tid = threadIdx.x;
    const size_t base = (size_t)row * HID;

    float v[16];
    float sum = 0.f, sq = 0.f;
#pragma unroll
    for (int i = 0; i < 16; i++) {
        const int idx = tid + i * 256;
        const float t = x[base + idx] + r[base + idx] + bias[idx];
        v[i] = t; sum += t; sq += t * t;
    }
    __shared__ float s1[8], s2[8];
#pragma unroll
    for (int o = 16; o > 0; o >>= 1) {
        sum += __shfl_xor_sync(0xffffffffu, sum, o);
        sq  += __shfl_xor_sync(0xffffffffu, sq, o);
    }
    if ((tid & 31) == 0) { s1[tid >> 5] = sum; s2[tid >> 5] = sq; }
    __syncthreads();
    float fs = 0.f, fq = 0.f;
#pragma unroll
    for (int i = 0; i < 8; i++) { fs += s1[i]; fq += s2[i]; }
    const float mu   = fs * (1.0f / HID);
    const float var  = fq * (1.0f / HID) - mu * mu;
    const float rstd = rsqrtf(var + LN_EPS);
#pragma unroll
    for (int i = 0; i < 16; i++) {
        const int idx = tid + i * 256;
        g_res[base + idx] = v[i];
        g_ln[base + idx]  = to_tf32((v[i] - mu) * rstd * gamma[idx] + beta[idx]);
    }
}

// ---------------------------------------------------------------------------
// Weight prep: dst[C][R] = tf32_rna(src[R][C])   (transpose + round)
// ---------------------------------------------------------------------------
__global__ __launch_bounds__(256) void transpose_rnd(
    const float* __restrict__ src, float* __restrict__ dst, int R, int C)
{
    __shared__ float t[32][33];
    const int tx = threadIdx.x & 31, ty = threadIdx.x >> 5;
    const int x  = blockIdx.x * 32 + tx;
    const int y0 = blockIdx.y * 32 + ty;
#pragma unroll
    for (int j = 0; j < 4; j++)
        t[ty + 8 * j][tx] = to_tf32(src[(size_t)(y0 + 8 * j) * C + x]);
    __syncthreads();
    const int x2 = blockIdx.y * 32 + tx;
    const int y2 = blockIdx.x * 32 + ty;
#pragma unroll
    for (int j = 0; j < 4; j++)
        dst[(size_t)(y2 + 8 * j) * R + x2] = t[tx][ty + 8 * j];
}

// ---------------------------------------------------------------------------
// TF32 mma.sync GEMM, cp.async 4-stage pipeline.
//   C[M,Ntot] = A[M,K] @ BT[Ntot,K]^T + epilogue
//   EPI==0: C = tf32(gelu(acc + bias[n]))
//   EPI==1: C = acc + resid[m,n] + bias[n]
// CTA tile 128x256x16, 8 warps (2x4), warp tile 64x64.
// Smem rows padded to 20 floats (80 B): conflict-free fragment LDS,
// 16B-aligned cp.async chunk addresses (80 = 5*16).
// ---------------------------------------------------------------------------
#define BM 128
#define BN 256
#define BK 16
#define PAD_ST 20
#define STAGE_BYTES ((BM + BN) * PAD_ST * 4)      // 30720
#define NSTG 4
#define GEMM_SMEM (NSTG * STAGE_BYTES)            // 122880

template <int EPI>
__global__ __launch_bounds__(256, 1) void gemm_mma(
    const float* __restrict__ A, const float* __restrict__ BT,
    const float* __restrict__ bias, const float* __restrict__ resid,
    float* __restrict__ C, int Ntot, int K, int NT)
{
    extern __shared__ char smem[];
    const unsigned smem_u32 = (unsigned)__cvta_generic_to_shared(smem);

    const int tid  = threadIdx.x;
    const int lane = tid & 31;
    const int warp = tid >> 5;
    const int g = lane >> 2;      // groupID (row within fragment)
    const int t = lane & 3;       // thread-in-group (col within fragment)
    const int wm = (warp >> 2) * 64;   // 2 warp-rows
    const int wn = (warp & 3) * 64;    // 4 warp-cols

    // band-of-8 raster (L2 reuse)
    const int lin  = blockIdx.x;
    const int band = lin / (8 * NT);
    const int rem  = lin - band * 8 * NT;
    const int m0   = (band * 8 + (rem & 7)) * BM;
    const int n0   = (rem >> 3) * BN;

    const int KT = K / BK;

    float acc[4][8][4];
#pragma unroll
    for (int i = 0; i < 4; i++)
#pragma unroll
        for (int j = 0; j < 8; j++)
#pragma unroll
            for (int k = 0; k < 4; k++) acc[i][j][k] = 0.f;

    // stage loader: A 128x16f (4 chunks/row), B 256x16f (4 chunks/row)
    auto issue_stage = [&](int slot, int kt) {
        const unsigned abase = smem_u32 + slot * STAGE_BYTES;
        const unsigned bbase = abase + BM * PAD_ST * 4;
        const int k0 = kt * BK;
#pragma unroll
        for (int i = 0; i < 2; i++) {            // A: 512 chunks
            const int idx = tid + i * 256;
            const int r = idx >> 2, c = idx & 3;
            cp16(abase + r * 80 + c * 16, A + (size_t)(m0 + r) * K + k0 + c * 4);
        }
#pragma unroll
        for (int i = 0; i < 4; i++) {            // B: 1024 chunks
            const int idx = tid + i * 256;
            const int r = idx >> 2, c = idx & 3;
            cp16(bbase + r * 80 + c * 16, BT + (size_t)(n0 + r) * K + k0 + c * 4);
        }
    };

    // prologue: stages 0..2
#pragma unroll
    for (int s = 0; s < NSTG - 1; s++) {
        issue_stage(s, s);
        asm volatile("cp.async.commit_group;" ::: "memory");
    }

#pragma unroll 1
    for (int kt = 0; kt < KT; kt++) {
        asm volatile("cp.async.wait_group %0;" :: "n"(NSTG - 2) : "memory");
        __syncthreads();

        // prefetch stage kt+3 into slot (kt+3)%4 == (kt-1)%4 (consumed last iter)
        if (kt + NSTG - 1 < KT)
            issue_stage((kt + NSTG - 1) & (NSTG - 1), kt + NSTG - 1);
        asm volatile("cp.async.commit_group;" ::: "memory");

        const int slot = kt & (NSTG - 1);
        const float* as = (const float*)(smem + slot * STAGE_BYTES);
        const float* bs = as + BM * PAD_ST;

#pragma unroll
        for (int ks = 0; ks < 2; ks++) {
            unsigned af[4][4], bf[8][2];
#pragma unroll
            for (int mt = 0; mt < 4; mt++) {
                const int rb = wm + mt * 16;
                af[mt][0] = __float_as_uint(as[(rb + g)     * PAD_ST + ks * 8 + t]);
                af[mt][1] = __float_as_uint(as[(rb + g + 8) * PAD_ST + ks * 8 + t]);
                af[mt][2] = __float_as_uint(as[(rb + g)     * PAD_ST + ks * 8 + t + 4]);
                af[mt][3] = __float_as_uint(as[(rb + g + 8) * PAD_ST + ks * 8 + t + 4]);
            }
#pragma unroll
            for (int nt = 0; nt < 8; nt++) {
                const int nb = wn + nt * 8;
                bf[nt][0] = __float_as_uint(bs[(nb + g) * PAD_ST + ks * 8 + t]);
                bf[nt][1] = __float_as_uint(bs[(nb + g) * PAD_ST + ks * 8 + t + 4]);
            }
#pragma unroll
            for (int mt = 0; mt < 4; mt++)
#pragma unroll
                for (int nt = 0; nt < 8; nt++) {
                    asm volatile(
                        "mma.sync.aligned.m16n8k8.row.col.f32.tf32.tf32.f32 "
                        "{%0,%1,%2,%3},{%4,%5,%6,%7},{%8,%9},{%0,%1,%2,%3};"
                        : "+f"(acc[mt][nt][0]), "+f"(acc[mt][nt][1]),
                          "+f"(acc[mt][nt][2]), "+f"(acc[mt][nt][3])
                        : "r"(af[mt][0]), "r"(af[mt][1]),
                          "r"(af[mt][2]), "r"(af[mt][3]),
                          "r"(bf[nt][0]), "r"(bf[nt][1]));
                }
        }
    }

    // epilogue: thread owns rows wm+mt*16+g(+8), cols wn+nt*8+2t(+1)
#pragma unroll
    for (int mt = 0; mt < 4; mt++) {
#pragma unroll
        for (int nt = 0; nt < 8; nt++) {
            const int col = n0 + wn + nt * 8 + 2 * t;
#pragma unroll
            for (int h = 0; h < 2; h++) {
                const int row = m0 + wm + mt * 16 + g + h * 8;
                const size_t off = (size_t)row * Ntot + col;
                float2 v;
                v.x = acc[mt][nt][h * 2 + 0];
                v.y = acc[mt][nt][h * 2 + 1];
                if (EPI == 0) {
                    v.x = to_tf32(gelu_tanh(v.x + bias[col]));
                    v.y = to_tf32(gelu_tanh(v.y + bias[col + 1]));
                } else {
                    v.x += resid[off]     + bias[col];
                    v.y += resid[off + 1] + bias[col + 1];
                }
                *(float2*)(C + off) = v;
            }
        }
    }
}

// ---------------------------------------------------------------------------
// Launch
// ---------------------------------------------------------------------------
extern "C" void kernel_launch(void* const* d_in, const int* in_sizes, int n_in,
                              void* d_out, int out_size)
{
    const float* input     = (const float*)d_in[0];
    const float* residual  = (const float*)d_in[1];
    // d_in[2] = residual_norm: unused by the reference
    const float* attn_bias = (const float*)d_in[3];
    const float* attn_nw   = (const float*)d_in[4];
    const float* attn_nb   = (const float*)d_in[5];
    const float* inter_w   = (const float*)d_in[6];
    const float* inter_b   = (const float*)d_in[7];
    const float* output_w  = (const float*)d_in[8];
    const float* output_b  = (const float*)d_in[9];
    float* out = (float*)d_out;

    float *ln_p, *res_p, *inter_p, *w1t_p, *w2t_p;
    cudaGetSymbolAddress((void**)&ln_p, g_ln);
    cudaGetSymbolAddress((void**)&res_p, g_res);
    cudaGetSymbolAddress((void**)&inter_p, g_inter);
    cudaGetSymbolAddress((void**)&w1t_p, g_w1t);
    cudaGetSymbolAddress((void**)&w2t_p, g_w2t);

    cudaFuncSetAttribute(gemm_mma<0>, cudaFuncAttributeMaxDynamicSharedMemorySize, GEMM_SMEM);
    cudaFuncSetAttribute(gemm_mma<1>, cudaFuncAttributeMaxDynamicSharedMemorySize, GEMM_SMEM);

    // weight prep: transpose + tf32 RNA round
    transpose_rnd<<<dim3(INT_DIM / 32, HID / 32), 256>>>(inter_w,  w1t_p, HID, INT_DIM);
    transpose_rnd<<<dim3(HID / 32, INT_DIM / 32), 256>>>(output_w, w2t_p, INT_DIM, HID);

    addln_kernel<<<MTOK, 256>>>(input, residual, attn_bias, attn_nw, attn_nb);

    // GEMM1: [8192,4096] x [4096,16384] -> g_inter (gelu, tf32-rounded)
    gemm_mma<0><<<(MTOK / BM) * (INT_DIM / BN), 256, GEMM_SMEM>>>(
        ln_p, w1t_p, inter_b, nullptr, inter_p, INT_DIM, HID, INT_DIM / BN);

    // GEMM2: [8192,16384] x [16384,4096] -> out (+res+bias)
    gemm_mma<1><<<(MTOK / BM) * (HID / BN), 256, GEMM_SMEM>>>(
        inter_p, w2t_p, output_b, res_p, out, HID, INT_DIM, HID / BN);
}

// round 10
// speedup vs baseline: 4.4014x; 1.9482x over previous
#include <cuda_runtime.h>
#include <cuda_fp16.h>
#include <math.h>
#include <stdint.h>

#define HID 4096
#define INT_DIM 16384
#define MTOK 8192
#define LN_EPS 1e-5f

// ---------------------------------------------------------------------------
// Scratch (__device__ globals: allocation-free rule)
// ---------------------------------------------------------------------------
__device__ float  g_res[(size_t)MTOK * HID];         // 128 MB fp32
__device__ __half g_ln[(size_t)MTOK * HID];          //  64 MB fp16
__device__ __half g_inter[(size_t)MTOK * INT_DIM];   // 256 MB fp16
__device__ __half g_w1t[(size_t)INT_DIM * HID];      // 128 MB  W1^T fp16
__device__ __half g_w2t[(size_t)HID * INT_DIM];      // 128 MB  W2^T fp16

__device__ __forceinline__ float gelu_tanh(float x) {
    float x3 = x * x * x;
    return 0.5f * x * (1.0f + tanhf(0.7978845608028654f * (x + 0.044715f * x3)));
}

__device__ __forceinline__ void cp16(unsigned dst, const void* src) {
    asm volatile("cp.async.cg.shared.global [%0], [%1], 16;" :: "r"(dst), "l"(src) : "memory");
}

// ---------------------------------------------------------------------------
// Kernel 1: res = input + residual + bias; ln = fp16(LN(res)*gamma + beta)
// ---------------------------------------------------------------------------
__global__ __launch_bounds__(256) void addln_kernel(
    const float* __restrict__ x, const float* __restrict__ r,
    const float* __restrict__ bias, const float* __restrict__ gamma,
    const float* __restrict__ beta)
{
    const int row = blockIdx.x;
    const int tid = threadIdx.x;
    const size_t base = (size_t)row * HID;

    float v[16];
    float sum = 0.f, sq = 0.f;
#pragma unroll
    for (int i = 0; i < 16; i++) {
        const int idx = tid + i * 256;
        const float t = x[base + idx] + r[base + idx] + bias[idx];
        v[i] = t; sum += t; sq += t * t;
    }
    __shared__ float s1[8], s2[8];
#pragma unroll
    for (int o = 16; o > 0; o >>= 1) {
        sum += __shfl_xor_sync(0xffffffffu, sum, o);
        sq  += __shfl_xor_sync(0xffffffffu, sq, o);
    }
    if ((tid & 31) == 0) { s1[tid >> 5] = sum; s2[tid >> 5] = sq; }
    __syncthreads();
    float fs = 0.f, fq = 0.f;
#pragma unroll
    for (int i = 0; i < 8; i++) { fs += s1[i]; fq += s2[i]; }
    const float mu   = fs * (1.0f / HID);
    const float var  = fq * (1.0f / HID) - mu * mu;
    const float rstd = rsqrtf(var + LN_EPS);
#pragma unroll
    for (int i = 0; i < 16; i++) {
        const int idx = tid + i * 256;
        g_res[base + idx] = v[i];
        g_ln[base + idx]  = __float2half_rn((v[i] - mu) * rstd * gamma[idx] + beta[idx]);
    }
}

// ---------------------------------------------------------------------------
// Weight prep: dst[C][R] = fp16(src[R][C])   (transpose + round)
// ---------------------------------------------------------------------------
__global__ __launch_bounds__(256) void transpose_h(
    const float* __restrict__ src, __half* __restrict__ dst, int R, int C)
{
    __shared__ float t[32][33];
    const int tx = threadIdx.x & 31, ty = threadIdx.x >> 5;
    const int x  = blockIdx.x * 32 + tx;
    const int y0 = blockIdx.y * 32 + ty;
#pragma unroll
    for (int j = 0; j < 4; j++)
        t[ty + 8 * j][tx] = src[(size_t)(y0 + 8 * j) * C + x];
    __syncthreads();
    const int x2 = blockIdx.y * 32 + tx;
    const int y2 = blockIdx.x * 32 + ty;
#pragma unroll
    for (int j = 0; j < 4; j++)
        dst[(size_t)(y2 + 8 * j) * R + x2] = __float2half_rn(t[tx][ty + 8 * j]);
}

// ---------------------------------------------------------------------------
// FP16 mma.sync m16n8k16 GEMM, cp.async 4-stage pipeline.
//   C[M,Ntot] = A[M,K] @ BT[Ntot,K]^T + epilogue   (A, BT fp16; acc fp32)
//   EPI==0: C(half)  = fp16(gelu(acc + bias[n]))
//   EPI==1: C(float) = acc + resid[m,n] + bias[n]
// CTA tile 128x256x32, 8 warps (2x4), warp tile 64x64.
// Smem rows = 40 halves (80 B = 5x16): conflict-free LDS.32 fragments,
// 16B-aligned cp.async chunks. Same 30KB/stage as tf32 but double K per stage.
// ---------------------------------------------------------------------------
#define BM 128
#define BN 256
#define BK 32
#define ST_H 40
#define STAGE_BYTES ((BM + BN) * ST_H * 2)        // 30720
#define NSTG 4
#define GEMM_SMEM (NSTG * STAGE_BYTES)            // 122880

template <int EPI>
__global__ __launch_bounds__(256, 1) void gemm_mma(
    const __half* __restrict__ A, const __half* __restrict__ BT,
    const float* __restrict__ bias, const float* __restrict__ resid,
    void* __restrict__ Cv, int Ntot, int K, int NT)
{
    extern __shared__ char smem[];
    const unsigned smem_u32 = (unsigned)__cvta_generic_to_shared(smem);

    const int tid  = threadIdx.x;
    const int lane = tid & 31;
    const int warp = tid >> 5;
    const int g = lane >> 2;           // fragment row
    const int t = lane & 3;            // fragment col group
    const int wm = (warp >> 2) * 64;
    const int wn = (warp & 3) * 64;

    // band-of-8 raster (L2 reuse)
    const int lin  = blockIdx.x;
    const int band = lin / (8 * NT);
    const int rem  = lin - band * 8 * NT;
    const int m0   = (band * 8 + (rem & 7)) * BM;
    const int n0   = (rem >> 3) * BN;

    const int KT = K / BK;

    float acc[4][8][4];
#pragma unroll
    for (int i = 0; i < 4; i++)
#pragma unroll
        for (int j = 0; j < 8; j++)
#pragma unroll
            for (int k = 0; k < 4; k++) acc[i][j][k] = 0.f;

    // stage loader: A 128 rows x 32 halves (4 chunks), B 256 rows x 4 chunks
    auto issue_stage = [&](int slot, int kt) {
        const unsigned abase = smem_u32 + slot * STAGE_BYTES;
        const unsigned bbase = abase + BM * ST_H * 2;
        const int k0 = kt * BK;
#pragma unroll
        for (int i = 0; i < 2; i++) {            // A: 512 chunks
            const int idx = tid + i * 256;
            const int r = idx >> 2, c = idx & 3;
            cp16(abase + r * 80 + c * 16, A + (size_t)(m0 + r) * K + k0 + c * 8);
        }
#pragma unroll
        for (int i = 0; i < 4; i++) {            // B: 1024 chunks
            const int idx = tid + i * 256;
            const int r = idx >> 2, c = idx & 3;
            cp16(bbase + r * 80 + c * 16, BT + (size_t)(n0 + r) * K + k0 + c * 8);
        }
    };

#pragma unroll
    for (int s = 0; s < NSTG - 1; s++) {
        issue_stage(s, s);
        asm volatile("cp.async.commit_group;" ::: "memory");
    }

#pragma unroll 1
    for (int kt = 0; kt < KT; kt++) {
        asm volatile("cp.async.wait_group %0;" :: "n"(NSTG - 2) : "memory");
        __syncthreads();

        if (kt + NSTG - 1 < KT)
            issue_stage((kt + NSTG - 1) & (NSTG - 1), kt + NSTG - 1);
        asm volatile("cp.async.commit_group;" ::: "memory");

        const int slot = kt & (NSTG - 1);
        const __half* as = (const __half*)(smem + slot * STAGE_BYTES);
        const __half* bs = as + BM * ST_H;

#pragma unroll
        for (int ks = 0; ks < 2; ks++) {         // two k16 steps per stage
            const int kb = ks * 16;
            unsigned af[4][4], bf[8][2];
#pragma unroll
            for (int mt = 0; mt < 4; mt++) {
                const int rb = wm + mt * 16;
                af[mt][0] = *(const unsigned*)(as + (rb + g)     * ST_H + kb + 2 * t);
                af[mt][1] = *(const unsigned*)(as + (rb + g + 8) * ST_H + kb + 2 * t);
                af[mt][2] = *(const unsigned*)(as + (rb + g)     * ST_H + kb + 2 * t + 8);
                af[mt][3] = *(const unsigned*)(as + (rb + g + 8) * ST_H + kb + 2 * t + 8);
            }
#pragma unroll
            for (int nt = 0; nt < 8; nt++) {
                const int nb = wn + nt * 8;
                bf[nt][0] = *(const unsigned*)(bs + (nb + g) * ST_H + kb + 2 * t);
                bf[nt][1] = *(const unsigned*)(bs + (nb + g) * ST_H + kb + 2 * t + 8);
            }
#pragma unroll
            for (int mt = 0; mt < 4; mt++)
#pragma unroll
                for (int nt = 0; nt < 8; nt++) {
                    asm volatile(
                        "mma.sync.aligned.m16n8k16.row.col.f32.f16.f16.f32 "
                        "{%0,%1,%2,%3},{%4,%5,%6,%7},{%8,%9},{%0,%1,%2,%3};"
                        : "+f"(acc[mt][nt][0]), "+f"(acc[mt][nt][1]),
                          "+f"(acc[mt][nt][2]), "+f"(acc[mt][nt][3])
                        : "r"(af[mt][0]), "r"(af[mt][1]),
                          "r"(af[mt][2]), "r"(af[mt][3]),
                          "r"(bf[nt][0]), "r"(bf[nt][1]));
                }
        }
    }

    // epilogue: thread owns rows wm+mt*16+g(+8), cols wn+nt*8+2t(+1)
#pragma unroll
    for (int mt = 0; mt < 4; mt++) {
#pragma unroll
        for (int nt = 0; nt < 8; nt++) {
            const int col = n0 + wn + nt * 8 + 2 * t;
#pragma unroll
            for (int h = 0; h < 2; h++) {
                const int row = m0 + wm + mt * 16 + g + h * 8;
                const size_t off = (size_t)row * Ntot + col;
                float vx = acc[mt][nt][h * 2 + 0];
                float vy = acc[mt][nt][h * 2 + 1];
                if (EPI == 0) {
                    __half2 o;
                    o.x = __float2half_rn(gelu_tanh(vx + bias[col]));
                    o.y = __float2half_rn(gelu_tanh(vy + bias[col + 1]));
                    *(__half2*)((__half*)Cv + off) = o;
                } else {
                    float2 o;
                    o.x = vx + resid[off]     + bias[col];
                    o.y = vy + resid[off + 1] + bias[col + 1];
                    *(float2*)((float*)Cv + off) = o;
                }
            }
        }
    }
}

// ---------------------------------------------------------------------------
// Launch
// ---------------------------------------------------------------------------
extern "C" void kernel_launch(void* const* d_in, const int* in_sizes, int n_in,
                              void* d_out, int out_size)
{
    const float* input     = (const float*)d_in[0];
    const float* residual  = (const float*)d_in[1];
    // d_in[2] = residual_norm: unused by the reference
    const float* attn_bias = (const float*)d_in[3];
    const float* attn_nw   = (const float*)d_in[4];
    const float* attn_nb   = (const float*)d_in[5];
    const float* inter_w   = (const float*)d_in[6];
    const float* inter_b   = (const float*)d_in[7];
    const float* output_w  = (const float*)d_in[8];
    const float* output_b  = (const float*)d_in[9];
    float* out = (float*)d_out;

    __half *ln_p, *inter_p, *w1t_p, *w2t_p;
    float *res_p;
    cudaGetSymbolAddress((void**)&ln_p, g_ln);
    cudaGetSymbolAddress((void**)&res_p, g_res);
    cudaGetSymbolAddress((void**)&inter_p, g_inter);
    cudaGetSymbolAddress((void**)&w1t_p, g_w1t);
    cudaGetSymbolAddress((void**)&w2t_p, g_w2t);

    cudaFuncSetAttribute(gemm_mma<0>, cudaFuncAttributeMaxDynamicSharedMemorySize, GEMM_SMEM);
    cudaFuncSetAttribute(gemm_mma<1>, cudaFuncAttributeMaxDynamicSharedMemorySize, GEMM_SMEM);

    // weight prep: transpose + fp16 round
    transpose_h<<<dim3(INT_DIM / 32, HID / 32), 256>>>(inter_w,  w1t_p, HID, INT_DIM);
    transpose_h<<<dim3(HID / 32, INT_DIM / 32), 256>>>(output_w, w2t_p, INT_DIM, HID);

    addln_kernel<<<MTOK, 256>>>(input, residual, attn_bias, attn_nw, attn_nb);

    // GEMM1: [8192,4096] x [4096,16384] -> g_inter (gelu, fp16)
    gemm_mma<0><<<(MTOK / BM) * (INT_DIM / BN), 256, GEMM_SMEM>>>(
        ln_p, w1t_p, inter_b, nullptr, inter_p, INT_DIM, HID, INT_DIM / BN);

    // GEMM2: [8192,16384] x [16384,4096] -> out (+res+bias, fp32)
    gemm_mma<1><<<(MTOK / BM) * (HID / BN), 256, GEMM_SMEM>>>(
        inter_p, w2t_p, output_b, res_p, out, HID, INT_DIM, HID / BN);
}

// round 11
// speedup vs baseline: 4.5572x; 1.0354x over previous
#include <cuda_runtime.h>
#include <cuda_fp16.h>
#include <math.h>
#include <stdint.h>

#define HID 4096
#define INT_DIM 16384
#define MTOK 8192
#define LN_EPS 1e-5f

// ---------------------------------------------------------------------------
// Scratch (__device__ globals: allocation-free rule)
// ---------------------------------------------------------------------------
__device__ float  g_res[(size_t)MTOK * HID];         // 128 MB fp32
__device__ __half g_ln[(size_t)MTOK * HID];          //  64 MB fp16
__device__ __half g_inter[(size_t)MTOK * INT_DIM];   // 256 MB fp16
__device__ __half g_w1t[(size_t)INT_DIM * HID];      // 128 MB  W1^T fp16
__device__ __half g_w2t[(size_t)HID * INT_DIM];      // 128 MB  W2^T fp16

__device__ __forceinline__ float gelu_tanh(float x) {
    float x3 = x * x * x;
    return 0.5f * x * (1.0f + tanhf(0.7978845608028654f * (x + 0.044715f * x3)));
}

__device__ __forceinline__ void cp16(unsigned dst, const void* src) {
    asm volatile("cp.async.cg.shared.global [%0], [%1], 16;" :: "r"(dst), "l"(src) : "memory");
}

__device__ __forceinline__ void ldsm4(unsigned& r0, unsigned& r1, unsigned& r2,
                                      unsigned& r3, unsigned addr) {
    asm volatile("ldmatrix.sync.aligned.m8n8.x4.shared.b16 {%0,%1,%2,%3}, [%4];"
                 : "=r"(r0), "=r"(r1), "=r"(r2), "=r"(r3) : "r"(addr));
}

// ---------------------------------------------------------------------------
// Kernel 1: res = input + residual + bias; ln = fp16(LN(res)*gamma + beta)
// ---------------------------------------------------------------------------
__global__ __launch_bounds__(256) void addln_kernel(
    const float* __restrict__ x, const float* __restrict__ r,
    const float* __restrict__ bias, const float* __restrict__ gamma,
    const float* __restrict__ beta)
{
    const int row = blockIdx.x;
    const int tid = threadIdx.x;
    const size_t base = (size_t)row * HID;

    float v[16];
    float sum = 0.f, sq = 0.f;
#pragma unroll
    for (int i = 0; i < 16; i++) {
        const int idx = tid + i * 256;
        const float t = x[base + idx] + r[base + idx] + bias[idx];
        v[i] = t; sum += t; sq += t * t;
    }
    __shared__ float s1[8], s2[8];
#pragma unroll
    for (int o = 16; o > 0; o >>= 1) {
        sum += __shfl_xor_sync(0xffffffffu, sum, o);
        sq  += __shfl_xor_sync(0xffffffffu, sq, o);
    }
    if ((tid & 31) == 0) { s1[tid >> 5] = sum; s2[tid >> 5] = sq; }
    __syncthreads();
    float fs = 0.f, fq = 0.f;
#pragma unroll
    for (int i = 0; i < 8; i++) { fs += s1[i]; fq += s2[i]; }
    const float mu   = fs * (1.0f / HID);
    const float var  = fq * (1.0f / HID) - mu * mu;
    const float rstd = rsqrtf(var + LN_EPS);
#pragma unroll
    for (int i = 0; i < 16; i++) {
        const int idx = tid + i * 256;
        g_res[base + idx] = v[i];
        g_ln[base + idx]  = __float2half_rn((v[i] - mu) * rstd * gamma[idx] + beta[idx]);
    }
}

// ---------------------------------------------------------------------------
// Weight prep: dst[C][R] = fp16(src[R][C])   (transpose + round)
// ---------------------------------------------------------------------------
__global__ __launch_bounds__(256) void transpose_h(
    const float* __restrict__ src, __half* __restrict__ dst, int R, int C)
{
    __shared__ float t[32][33];
    const int tx = threadIdx.x & 31, ty = threadIdx.x >> 5;
    const int x  = blockIdx.x * 32 + tx;
    const int y0 = blockIdx.y * 32 + ty;
#pragma unroll
    for (int j = 0; j < 4; j++)
        t[ty + 8 * j][tx] = src[(size_t)(y0 + 8 * j) * C + x];
    __syncthreads();
    const int x2 = blockIdx.y * 32 + tx;
    const int y2 = blockIdx.x * 32 + ty;
#pragma unroll
    for (int j = 0; j < 4; j++)
        dst[(size_t)(y2 + 8 * j) * R + x2] = __float2half_rn(t[tx][ty + 8 * j]);
}

// ---------------------------------------------------------------------------
// FP16 mma.sync m16n8k16 GEMM, cp.async 4-stage pipeline, ldmatrix fragments.
//   C[M,Ntot] = A[M,K] @ BT[Ntot,K]^T + epilogue   (A, BT fp16; acc fp32)
//   EPI==0: C(half)  = fp16(gelu(acc + bias[n]))
//   EPI==1: C(float) = acc + resid[m,n] + bias[n]
// CTA tile 128x256x32, 8 warps (2x4), warp tile 64x64.
// Smem rows = 40 halves (80 B): ldmatrix row-chunks hit disjoint bank phases
// {0,20,8,28,16,4,24,12} -> conflict-free LDSM; 16B-aligned cp.async chunks.
// Per k16 step: 8 LDSM.x4 + 32 HMMA (was 32 LDS.32 + 32 HMMA).
// ---------------------------------------------------------------------------
#define BM 128
#define BN 256
#define BK 32
#define ST_H 40
#define ROW_B 80
#define STAGE_BYTES ((BM + BN) * ST_H * 2)        // 30720
#define NSTG 4
#define GEMM_SMEM (NSTG * STAGE_BYTES)            // 122880

template <int EPI>
__global__ __launch_bounds__(256, 1) void gemm_mma(
    const __half* __restrict__ A, const __half* __restrict__ BT,
    const float* __restrict__ bias, const float* __restrict__ resid,
    void* __restrict__ Cv, int Ntot, int K, int NT)
{
    extern __shared__ char smem[];
    const unsigned smem_u32 = (unsigned)__cvta_generic_to_shared(smem);

    const int tid  = threadIdx.x;
    const int lane = tid & 31;
    const int warp = tid >> 5;
    const int g = lane >> 2;           // fragment row (epilogue)
    const int t = lane & 3;            // fragment col group (epilogue)
    const int wm = (warp >> 2) * 64;
    const int wn = (warp & 3) * 64;

    // band-of-8 raster (L2 reuse)
    const int lin  = blockIdx.x;
    const int band = lin / (8 * NT);
    const int rem  = lin - band * 8 * NT;
    const int m0   = (band * 8 + (rem & 7)) * BM;
    const int n0   = (rem >> 3) * BN;

    const int KT = K / BK;

    // ldmatrix per-lane byte offsets (within a stage), ks-invariant parts.
    // A tile mt: matrices {rows rb..+7,k0..7},{rows+8,k0..7},{rows,k8..15},{rows+8,k8..15}
    //   lane: bit3 -> +8 rows, bit4 -> +8 cols
    // B pair p (nt=2p,2p+1): matrices {n..+7,k0..7},{n..+7,k8..15},{n+8..,k0..7},{n+8..,k8..15}
    //   lane: bit3 -> +8 cols, bit4 -> +8 rows
    const int l7 = lane & 7;
    unsigned offA[4], offB[4];
#pragma unroll
    for (int mt = 0; mt < 4; mt++) {
        const int rowa = wm + mt * 16 + l7 + 8 * ((lane >> 3) & 1);
        offA[mt] = rowa * ROW_B + (((lane >> 4) & 1) * 8) * 2;
    }
#pragma unroll
    for (int p = 0; p < 4; p++) {
        const int rowb = wn + p * 16 + l7 + 8 * ((lane >> 4) & 1);
        offB[p] = BM * ROW_B + rowb * ROW_B + (((lane >> 3) & 1) * 8) * 2;
    }

    float acc[4][8][4];
#pragma unroll
    for (int i = 0; i < 4; i++)
#pragma unroll
        for (int j = 0; j < 8; j++)
#pragma unroll
            for (int k = 0; k < 4; k++) acc[i][j][k] = 0.f;

    // stage loader: A 128 rows x 32 halves (4 chunks), B 256 rows x 4 chunks
    auto issue_stage = [&](int slot, int kt) {
        const unsigned abase = smem_u32 + slot * STAGE_BYTES;
        const unsigned bbase = abase + BM * ROW_B;
        const int k0 = kt * BK;
#pragma unroll
        for (int i = 0; i < 2; i++) {            // A: 512 chunks
            const int idx = tid + i * 256;
            const int r = idx >> 2, c = idx & 3;
            cp16(abase + r * ROW_B + c * 16, A + (size_t)(m0 + r) * K + k0 + c * 8);
        }
#pragma unroll
        for (int i = 0; i < 4; i++) {            // B: 1024 chunks
            const int idx = tid + i * 256;
            const int r = idx >> 2, c = idx & 3;
            cp16(bbase + r * ROW_B + c * 16, BT + (size_t)(n0 + r) * K + k0 + c * 8);
        }
    };

#pragma unroll
    for (int s = 0; s < NSTG - 1; s++) {
        issue_stage(s, s);
        asm volatile("cp.async.commit_group;" ::: "memory");
    }

#pragma unroll 1
    for (int kt = 0; kt < KT; kt++) {
        asm volatile("cp.async.wait_group %0;" :: "n"(NSTG - 2) : "memory");
        __syncthreads();

        if (kt + NSTG - 1 < KT)
            issue_stage((kt + NSTG - 1) & (NSTG - 1), kt + NSTG - 1);
        asm volatile("cp.async.commit_group;" ::: "memory");

        const int slot = kt & (NSTG - 1);
        const unsigned sbase = smem_u32 + slot * STAGE_BYTES;

#pragma unroll
        for (int ks = 0; ks < 2; ks++) {         // two k16 steps per stage
            const unsigned kadd = ks * 32;       // 16 halves
            unsigned af[4][4], bf[8][2];
#pragma unroll
            for (int mt = 0; mt < 4; mt++)
                ldsm4(af[mt][0], af[mt][1], af[mt][2], af[mt][3],
                      sbase + offA[mt] + kadd);
#pragma unroll
            for (int p = 0; p < 4; p++)
                ldsm4(bf[2 * p][0], bf[2 * p][1], bf[2 * p + 1][0], bf[2 * p + 1][1],
                      sbase + offB[p] + kadd);
#pragma unroll
            for (int mt = 0; mt < 4; mt++)
#pragma unroll
                for (int nt = 0; nt < 8; nt++) {
                    asm volatile(
                        "mma.sync.aligned.m16n8k16.row.col.f32.f16.f16.f32 "
                        "{%0,%1,%2,%3},{%4,%5,%6,%7},{%8,%9},{%0,%1,%2,%3};"
                        : "+f"(acc[mt][nt][0]), "+f"(acc[mt][nt][1]),
                          "+f"(acc[mt][nt][2]), "+f"(acc[mt][nt][3])
                        : "r"(af[mt][0]), "r"(af[mt][1]),
                          "r"(af[mt][2]), "r"(af[mt][3]),
                          "r"(bf[nt][0]), "r"(bf[nt][1]));
                }
        }
    }

    // epilogue: thread owns rows wm+mt*16+g(+8), cols wn+nt*8+2t(+1)
#pragma unroll
    for (int mt = 0; mt < 4; mt++) {
#pragma unroll
        for (int nt = 0; nt < 8; nt++) {
            const int col = n0 + wn + nt * 8 + 2 * t;
#pragma unroll
            for (int h = 0; h < 2; h++) {
                const int row = m0 + wm + mt * 16 + g + h * 8;
                const size_t off = (size_t)row * Ntot + col;
                float vx = acc[mt][nt][h * 2 + 0];
                float vy = acc[mt][nt][h * 2 + 1];
                if (EPI == 0) {
                    __half2 o;
                    o.x = __float2half_rn(gelu_tanh(vx + bias[col]));
                    o.y = __float2half_rn(gelu_tanh(vy + bias[col + 1]));
                    *(__half2*)((__half*)Cv + off) = o;
                } else {
                    float2 o;
                    o.x = vx + resid[off]     + bias[col];
                    o.y = vy + resid[off + 1] + bias[col + 1];
                    *(float2*)((float*)Cv + off) = o;
                }
            }
        }
    }
}

// ---------------------------------------------------------------------------
// Launch
// ---------------------------------------------------------------------------
extern "C" void kernel_launch(void* const* d_in, const int* in_sizes, int n_in,
                              void* d_out, int out_size)
{
    const float* input     = (const float*)d_in[0];
    const float* residual  = (const float*)d_in[1];
    // d_in[2] = residual_norm: unused by the reference
    const float* attn_bias = (const float*)d_in[3];
    const float* attn_nw   = (const float*)d_in[4];
    const float* attn_nb   = (const float*)d_in[5];
    const float* inter_w   = (const float*)d_in[6];
    const float* inter_b   = (const float*)d_in[7];
    const float* output_w  = (const float*)d_in[8];
    const float* output_b  = (const float*)d_in[9];
    float* out = (float*)d_out;

    __half *ln_p, *inter_p, *w1t_p, *w2t_p;
    float *res_p;
    cudaGetSymbolAddress((void**)&ln_p, g_ln);
    cudaGetSymbolAddress((void**)&res_p, g_res);
    cudaGetSymbolAddress((void**)&inter_p, g_inter);
    cudaGetSymbolAddress((void**)&w1t_p, g_w1t);
    cudaGetSymbolAddress((void**)&w2t_p, g_w2t);

    cudaFuncSetAttribute(gemm_mma<0>, cudaFuncAttributeMaxDynamicSharedMemorySize, GEMM_SMEM);
    cudaFuncSetAttribute(gemm_mma<1>, cudaFuncAttributeMaxDynamicSharedMemorySize, GEMM_SMEM);

    // weight prep: transpose + fp16 round
    transpose_h<<<dim3(INT_DIM / 32, HID / 32), 256>>>(inter_w,  w1t_p, HID, INT_DIM);
    transpose_h<<<dim3(HID / 32, INT_DIM / 32), 256>>>(output_w, w2t_p, INT_DIM, HID);

    addln_kernel<<<MTOK, 256>>>(input, residual, attn_bias, attn_nw, attn_nb);

    // GEMM1: [8192,4096] x [4096,16384] -> g_inter (gelu, fp16)
    gemm_mma<0><<<(MTOK / BM) * (INT_DIM / BN), 256, GEMM_SMEM>>>(
        ln_p, w1t_p, inter_b, nullptr, inter_p, INT_DIM, HID, INT_DIM / BN);

    // GEMM2: [8192,16384] x [16384,4096] -> out (+res+bias, fp32)
    gemm_mma<1><<<(MTOK / BM) * (HID / BN), 256, GEMM_SMEM>>>(
        inter_p, w2t_p, output_b, res_p, out, HID, INT_DIM, HID / BN);
}

// round 12
// speedup vs baseline: 5.1550x; 1.1312x over previous
#include <cuda_runtime.h>
#include <cuda_fp16.h>
#include <math.h>
#include <stdint.h>

#define HID 4096
#define INT_DIM 16384
#define MTOK 8192
#define LN_EPS 1e-5f

// ---------------------------------------------------------------------------
// Scratch (__device__ globals: allocation-free rule)
// ---------------------------------------------------------------------------
__device__ float  g_res[(size_t)MTOK * HID];         // 128 MB fp32
__device__ __half g_ln[(size_t)MTOK * HID];          //  64 MB fp16
__device__ __half g_inter[(size_t)MTOK * INT_DIM];   // 256 MB fp16
__device__ __half g_w1t[(size_t)INT_DIM * HID];      // 128 MB  W1^T fp16
__device__ __half g_w2t[(size_t)HID * INT_DIM];      // 128 MB  W2^T fp16

__device__ __forceinline__ float gelu_tanh(float x) {
    float x3 = x * x * x;
    return 0.5f * x * (1.0f + tanhf(0.7978845608028654f * (x + 0.044715f * x3)));
}

__device__ __forceinline__ void cp16(unsigned dst, const void* src) {
    asm volatile("cp.async.cg.shared.global [%0], [%1], 16;" :: "r"(dst), "l"(src) : "memory");
}

__device__ __forceinline__ void ldsm4(unsigned& r0, unsigned& r1, unsigned& r2,
                                      unsigned& r3, unsigned addr) {
    asm volatile("ldmatrix.sync.aligned.m8n8.x4.shared.b16 {%0,%1,%2,%3}, [%4];"
                 : "=r"(r0), "=r"(r1), "=r"(r2), "=r"(r3) : "r"(addr));
}

// ---------------------------------------------------------------------------
// Kernel 1: res = input + residual + bias; ln = fp16(LN(res)*gamma + beta)
// ---------------------------------------------------------------------------
__global__ __launch_bounds__(256) void addln_kernel(
    const float* __restrict__ x, const float* __restrict__ r,
    const float* __restrict__ bias, const float* __restrict__ gamma,
    const float* __restrict__ beta)
{
    const int row = blockIdx.x;
    const int tid = threadIdx.x;
    const size_t base = (size_t)row * HID;

    float v[16];
    float sum = 0.f, sq = 0.f;
#pragma unroll
    for (int i = 0; i < 16; i++) {
        const int idx = tid + i * 256;
        const float t = x[base + idx] + r[base + idx] + bias[idx];
        v[i] = t; sum += t; sq += t * t;
    }
    __shared__ float s1[8], s2[8];
#pragma unroll
    for (int o = 16; o > 0; o >>= 1) {
        sum += __shfl_xor_sync(0xffffffffu, sum, o);
        sq  += __shfl_xor_sync(0xffffffffu, sq, o);
    }
    if ((tid & 31) == 0) { s1[tid >> 5] = sum; s2[tid >> 5] = sq; }
    __syncthreads();
    float fs = 0.f, fq = 0.f;
#pragma unroll
    for (int i = 0; i < 8; i++) { fs += s1[i]; fq += s2[i]; }
    const float mu   = fs * (1.0f / HID);
    const float var  = fq * (1.0f / HID) - mu * mu;
    const float rstd = rsqrtf(var + LN_EPS);
#pragma unroll
    for (int i = 0; i < 16; i++) {
        const int idx = tid + i * 256;
        g_res[base + idx] = v[i];
        g_ln[base + idx]  = __float2half_rn((v[i] - mu) * rstd * gamma[idx] + beta[idx]);
    }
}

// ---------------------------------------------------------------------------
// Weight prep: dst[C][R] = fp16(src[R][C])   (transpose + round)
// ---------------------------------------------------------------------------
__global__ __launch_bounds__(256) void transpose_h(
    const float* __restrict__ src, __half* __restrict__ dst, int R, int C)
{
    __shared__ float t[32][33];
    const int tx = threadIdx.x & 31, ty = threadIdx.x >> 5;
    const int x  = blockIdx.x * 32 + tx;
    const int y0 = blockIdx.y * 32 + ty;
#pragma unroll
    for (int j = 0; j < 4; j++)
        t[ty + 8 * j][tx] = src[(size_t)(y0 + 8 * j) * C + x];
    __syncthreads();
    const int x2 = blockIdx.y * 32 + tx;
    const int y2 = blockIdx.x * 32 + ty;
#pragma unroll
    for (int j = 0; j < 4; j++)
        dst[(size_t)(y2 + 8 * j) * R + x2] = __float2half_rn(t[tx][ty + 8 * j]);
}

// ---------------------------------------------------------------------------
// FP16 mma.sync m16n8k16 GEMM; cp.async 3-stage BK=64 ring; ldmatrix
// fragments software-pipelined one k16-step ahead (ping-pong buffers).
//   C[M,Ntot] = A[M,K] @ BT[Ntot,K]^T + epilogue   (A, BT fp16; acc fp32)
//   EPI==0: C(half)  = fp16(gelu(acc + bias[n]))
//   EPI==1: C(float) = acc + resid[m,n] + bias[n]
// CTA tile 128x256x64, 8 warps (2x4), warp tile 64x64.
// Smem rows = 72 halves (144 B): ldmatrix chunk phases {0,16,..,112} mod 128
// -> conflict-free; cp.async chunks 16B-aligned (144 = 9*16).
// ---------------------------------------------------------------------------
#define BM 128
#define BN 256
#define BK 64
#define ROW_H 72
#define ROW_B 144
#define STAGE_BYTES ((BM + BN) * ROW_B)           // 55296
#define NSTG 3
#define GEMM_SMEM (NSTG * STAGE_BYTES)            // 165888

template <int EPI>
__global__ __launch_bounds__(256, 1) void gemm_mma(
    const __half* __restrict__ A, const __half* __restrict__ BT,
    const float* __restrict__ bias, const float* __restrict__ resid,
    void* __restrict__ Cv, int Ntot, int K, int NT)
{
    extern __shared__ char smem[];
    const unsigned smem_u32 = (unsigned)__cvta_generic_to_shared(smem);

    const int tid  = threadIdx.x;
    const int lane = tid & 31;
    const int warp = tid >> 5;
    const int g = lane >> 2;
    const int t = lane & 3;
    const int wm = (warp >> 2) * 64;
    const int wn = (warp & 3) * 64;

    // band-of-8 raster (L2 reuse)
    const int lin  = blockIdx.x;
    const int band = lin / (8 * NT);
    const int rem  = lin - band * 8 * NT;
    const int m0   = (band * 8 + (rem & 7)) * BM;
    const int n0   = (rem >> 3) * BN;

    const int KT = K / BK;

    // ldmatrix per-lane byte offsets (stage-relative, k-step invariant)
    const int l7 = lane & 7;
    unsigned offA[4], offB[4];
#pragma unroll
    for (int mt = 0; mt < 4; mt++) {
        const int rowa = wm + mt * 16 + l7 + 8 * ((lane >> 3) & 1);
        offA[mt] = rowa * ROW_B + (((lane >> 4) & 1) * 8) * 2;
    }
#pragma unroll
    for (int p = 0; p < 4; p++) {
        const int rowb = wn + p * 16 + l7 + 8 * ((lane >> 4) & 1);
        offB[p] = BM * ROW_B + rowb * ROW_B + (((lane >> 3) & 1) * 8) * 2;
    }

    float acc[4][8][4];
#pragma unroll
    for (int i = 0; i < 4; i++)
#pragma unroll
        for (int j = 0; j < 8; j++)
#pragma unroll
            for (int k = 0; k < 4; k++) acc[i][j][k] = 0.f;

    // fragment ping-pong buffers
    unsigned af[2][4][4], bf[2][8][2];

    // stage loader: A 128 rows x 8 chunks, B 256 rows x 8 chunks (16B each)
    auto issue_stage = [&](int slot, int kt) {
        const unsigned abase = smem_u32 + slot * STAGE_BYTES;
        const unsigned bbase = abase + BM * ROW_B;
        const int k0 = kt * BK;
#pragma unroll
        for (int i = 0; i < 4; i++) {            // A: 1024 chunks
            const int idx = tid + i * 256;
            const int r = idx >> 3, c = idx & 7;
            cp16(abase + r * ROW_B + c * 16, A + (size_t)(m0 + r) * K + k0 + c * 8);
        }
#pragma unroll
        for (int i = 0; i < 8; i++) {            // B: 2048 chunks
            const int idx = tid + i * 256;
            const int r = idx >> 3, c = idx & 7;
            cp16(bbase + r * ROW_B + c * 16, BT + (size_t)(n0 + r) * K + k0 + c * 8);
        }
    };

    // fragment prefetch for one k16 step
    auto load_frags = [&](int buf, unsigned sbase, int ks) {
        const unsigned kadd = ks * 32;           // 16 halves
#pragma unroll
        for (int mt = 0; mt < 4; mt++)
            ldsm4(af[buf][mt][0], af[buf][mt][1], af[buf][mt][2], af[buf][mt][3],
                  sbase + offA[mt] + kadd);
#pragma unroll
        for (int p = 0; p < 4; p++)
            ldsm4(bf[buf][2 * p][0], bf[buf][2 * p][1],
                  bf[buf][2 * p + 1][0], bf[buf][2 * p + 1][1],
                  sbase + offB[p] + kadd);
    };

    auto mma_step = [&](int buf) {
#pragma unroll
        for (int mt = 0; mt < 4; mt++)
#pragma unroll
            for (int nt = 0; nt < 8; nt++) {
                asm volatile(
                    "mma.sync.aligned.m16n8k16.row.col.f32.f16.f16.f32 "
                    "{%0,%1,%2,%3},{%4,%5,%6,%7},{%8,%9},{%0,%1,%2,%3};"
                    : "+f"(acc[mt][nt][0]), "+f"(acc[mt][nt][1]),
                      "+f"(acc[mt][nt][2]), "+f"(acc[mt][nt][3])
                    : "r"(af[buf][mt][0]), "r"(af[buf][mt][1]),
                      "r"(af[buf][mt][2]), "r"(af[buf][mt][3]),
                      "r"(bf[buf][nt][0]), "r"(bf[buf][nt][1]));
            }
    };

    // prologue: stages 0,1
    issue_stage(0, 0);
    asm volatile("cp.async.commit_group;" ::: "memory");
    issue_stage(1, 1);
    asm volatile("cp.async.commit_group;" ::: "memory");

    int slot = 0;
#pragma unroll 1
    for (int kt = 0; kt < KT; kt++) {
        asm volatile("cp.async.wait_group 1;" ::: "memory");
        __syncthreads();

        if (kt + 2 < KT) {
            int ns = slot + 2; if (ns >= NSTG) ns -= NSTG;
            issue_stage(ns, kt + 2);
        }
        asm volatile("cp.async.commit_group;" ::: "memory");

        const unsigned sbase = smem_u32 + slot * STAGE_BYTES;

        load_frags(0, sbase, 0);                 // first k-step exposed
#pragma unroll
        for (int ks = 0; ks < BK / 16; ks++) {   // 4 k16 steps
            if (ks + 1 < BK / 16)
                load_frags((ks + 1) & 1, sbase, ks + 1);  // prefetch next
            mma_step(ks & 1);                    // overlap with LDSM latency
        }

        if (++slot == NSTG) slot = 0;
    }

    // epilogue: thread owns rows wm+mt*16+g(+8), cols wn+nt*8+2t(+1)
#pragma unroll
    for (int mt = 0; mt < 4; mt++) {
#pragma unroll
        for (int nt = 0; nt < 8; nt++) {
            const int col = n0 + wn + nt * 8 + 2 * t;
#pragma unroll
            for (int h = 0; h < 2; h++) {
                const int row = m0 + wm + mt * 16 + g + h * 8;
                const size_t off = (size_t)row * Ntot + col;
                float vx = acc[mt][nt][h * 2 + 0];
                float vy = acc[mt][nt][h * 2 + 1];
                if (EPI == 0) {
                    __half2 o;
                    o.x = __float2half_rn(gelu_tanh(vx + bias[col]));
                    o.y = __float2half_rn(gelu_tanh(vy + bias[col + 1]));
                    *(__half2*)((__half*)Cv + off) = o;
                } else {
                    float2 o;
                    o.x = vx + resid[off]     + bias[col];
                    o.y = vy + resid[off + 1] + bias[col + 1];
                    *(float2*)((float*)Cv + off) = o;
                }
            }
        }
    }
}

// ---------------------------------------------------------------------------
// Launch
// ---------------------------------------------------------------------------
extern "C" void kernel_launch(void* const* d_in, const int* in_sizes, int n_in,
                              void* d_out, int out_size)
{
    const float* input     = (const float*)d_in[0];
    const float* residual  = (const float*)d_in[1];
    // d_in[2] = residual_norm: unused by the reference
    const float* attn_bias = (const float*)d_in[3];
    const float* attn_nw   = (const float*)d_in[4];
    const float* attn_nb   = (const float*)d_in[5];
    const float* inter_w   = (const float*)d_in[6];
    const float* inter_b   = (const float*)d_in[7];
    const float* output_w  = (const float*)d_in[8];
    const float* output_b  = (const float*)d_in[9];
    float* out = (float*)d_out;

    __half *ln_p, *inter_p, *w1t_p, *w2t_p;
    float *res_p;
    cudaGetSymbolAddress((void**)&ln_p, g_ln);
    cudaGetSymbolAddress((void**)&res_p, g_res);
    cudaGetSymbolAddress((void**)&inter_p, g_inter);
    cudaGetSymbolAddress((void**)&w1t_p, g_w1t);
    cudaGetSymbolAddress((void**)&w2t_p, g_w2t);

    cudaFuncSetAttribute(gemm_mma<0>, cudaFuncAttributeMaxDynamicSharedMemorySize, GEMM_SMEM);
    cudaFuncSetAttribute(gemm_mma<1>, cudaFuncAttributeMaxDynamicSharedMemorySize, GEMM_SMEM);

    // weight prep: transpose + fp16 round
    transpose_h<<<dim3(INT_DIM / 32, HID / 32), 256>>>(inter_w,  w1t_p, HID, INT_DIM);
    transpose_h<<<dim3(HID / 32, INT_DIM / 32), 256>>>(output_w, w2t_p, INT_DIM, HID);

    addln_kernel<<<MTOK, 256>>>(input, residual, attn_bias, attn_nw, attn_nb);

    // GEMM1: [8192,4096] x [4096,16384] -> g_inter (gelu, fp16)
    gemm_mma<0><<<(MTOK / BM) * (INT_DIM / BN), 256, GEMM_SMEM>>>(
        ln_p, w1t_p, inter_b, nullptr, inter_p, INT_DIM, HID, INT_DIM / BN);

    // GEMM2: [8192,16384] x [16384,4096] -> out (+res+bias, fp32)
    gemm_mma<1><<<(MTOK / BM) * (HID / BN), 256, GEMM_SMEM>>>(
        inter_p, w2t_p, output_b, res_p, out, HID, INT_DIM, HID / BN);
}

// round 14
// speedup vs baseline: 6.7628x; 1.3119x over previous
#include <cuda_runtime.h>
#include <cuda_fp16.h>
#include <math.h>
#include <stdint.h>

#define HID 4096
#define INT_DIM 16384
#define MTOK 8192
#define LN_EPS 1e-5f

// ---------------------------------------------------------------------------
// Scratch (__device__ globals: allocation-free rule)
// ---------------------------------------------------------------------------
__device__ float  g_res[(size_t)MTOK * HID];         // 128 MB fp32
__device__ __half g_ln[(size_t)MTOK * HID];          //  64 MB fp16
__device__ __half g_inter[(size_t)MTOK * INT_DIM];   // 256 MB fp16
__device__ __half g_w1t[(size_t)INT_DIM * HID];      // 128 MB  W1^T fp16
__device__ __half g_w2t[(size_t)HID * INT_DIM];      // 128 MB  W2^T fp16

__device__ __forceinline__ float gelu_tanh(float x) {
    float x3 = x * x * x;
    return 0.5f * x * (1.0f + tanhf(0.7978845608028654f * (x + 0.044715f * x3)));
}

__device__ __forceinline__ void cp16(unsigned dst, const void* src) {
    asm volatile("cp.async.cg.shared.global [%0], [%1], 16;" :: "r"(dst), "l"(src) : "memory");
}

__device__ __forceinline__ void ldsm4(unsigned& r0, unsigned& r1, unsigned& r2,
                                      unsigned& r3, unsigned addr) {
    asm volatile("ldmatrix.sync.aligned.m8n8.x4.shared.b16 {%0,%1,%2,%3}, [%4];"
                 : "=r"(r0), "=r"(r1), "=r"(r2), "=r"(r3) : "r"(addr));
}

// ---------------------------------------------------------------------------
// Kernel 1: res = input + residual + bias; ln = fp16(LN(res)*gamma + beta)
// ---------------------------------------------------------------------------
__global__ __launch_bounds__(256) void addln_kernel(
    const float* __restrict__ x, const float* __restrict__ r,
    const float* __restrict__ bias, const float* __restrict__ gamma,
    const float* __restrict__ beta)
{
    const int row = blockIdx.x;
    const int tid = threadIdx.x;
    const size_t base = (size_t)row * HID;

    float v[16];
    float sum = 0.f, sq = 0.f;
#pragma unroll
    for (int i = 0; i < 16; i++) {
        const int idx = tid + i * 256;
        const float t = x[base + idx] + r[base + idx] + bias[idx];
        v[i] = t; sum += t; sq += t * t;
    }
    __shared__ float s1[8], s2[8];
#pragma unroll
    for (int o = 16; o > 0; o >>= 1) {
        sum += __shfl_xor_sync(0xffffffffu, sum, o);
        sq  += __shfl_xor_sync(0xffffffffu, sq, o);
    }
    if ((tid & 31) == 0) { s1[tid >> 5] = sum; s2[tid >> 5] = sq; }
    __syncthreads();
    float fs = 0.f, fq = 0.f;
#pragma unroll
    for (int i = 0; i < 8; i++) { fs += s1[i]; fq += s2[i]; }
    const float mu   = fs * (1.0f / HID);
    const float var  = fq * (1.0f / HID) - mu * mu;
    const float rstd = rsqrtf(var + LN_EPS);
#pragma unroll
    for (int i = 0; i < 16; i++) {
        const int idx = tid + i * 256;
        g_res[base + idx] = v[i];
        g_ln[base + idx]  = __float2half_rn((v[i] - mu) * rstd * gamma[idx] + beta[idx]);
    }
}

// ---------------------------------------------------------------------------
// Weight prep: dst[C][R] = fp16(src[R][C])   (transpose + round)
// ---------------------------------------------------------------------------
__global__ __launch_bounds__(256) void transpose_h(
    const float* __restrict__ src, __half* __restrict__ dst, int R, int C)
{
    __shared__ float t[32][33];
    const int tx = threadIdx.x & 31, ty = threadIdx.x >> 5;
    const int x  = blockIdx.x * 32 + tx;
    const int y0 = blockIdx.y * 32 + ty;
#pragma unroll
    for (int j = 0; j < 4; j++)
        t[ty + 8 * j][tx] = src[(size_t)(y0 + 8 * j) * C + x];
    __syncthreads();
    const int x2 = blockIdx.y * 32 + tx;
    const int y2 = blockIdx.x * 32 + ty;
#pragma unroll
    for (int j = 0; j < 4; j++)
        dst[(size_t)(y2 + 8 * j) * R + x2] = __float2half_rn(t[tx][ty + 8 * j]);
}

// ---------------------------------------------------------------------------
// FP16 mma.sync m16n8k16 GEMM; cp.async 3-stage BK=64 ring; ldmatrix
// fragment pipeline kept primed ACROSS stage boundaries (CUTLASS multistage
// order): wait+bar+next-stage-ks0-prefetch happen BEFORE the last MMA step
// of each stage, so only the barrier itself is exposed.
//   C[M,Ntot] = A[M,K] @ BT[Ntot,K]^T + epilogue   (A, BT fp16; acc fp32)
//   EPI==0: C(half)  = fp16(gelu(acc + bias[n]))
//   EPI==1: C(float) = acc + resid[m,n] + bias[n]
// CTA tile 128x256x64, 8 warps (2x4), warp tile 64x64.
// Smem rows = 72 halves (144 B): ldmatrix chunk phases conflict-free;
// cp.async chunks 16B-aligned (144 = 9*16).
// ---------------------------------------------------------------------------
#define BM 128
#define BN 256
#define BK 64
#define ROW_H 72
#define ROW_B 144
#define STAGE_BYTES ((BM + BN) * ROW_B)           // 55296
#define NSTG 3
#define GEMM_SMEM (NSTG * STAGE_BYTES)            // 165888

template <int EPI>
__global__ __launch_bounds__(256, 1) void gemm_mma(
    const __half* __restrict__ A, const __half* __restrict__ BT,
    const float* __restrict__ bias, const float* __restrict__ resid,
    void* __restrict__ Cv, int Ntot, int K, int NT)
{
    extern __shared__ char smem[];
    const unsigned smem_u32 = (unsigned)__cvta_generic_to_shared(smem);

    const int tid  = threadIdx.x;
    const int lane = tid & 31;
    const int warp = tid >> 5;
    const int g = lane >> 2;
    const int t = lane & 3;
    const int wm = (warp >> 2) * 64;
    const int wn = (warp & 3) * 64;

    // band-of-8 raster (L2 reuse)
    const int lin  = blockIdx.x;
    const int band = lin / (8 * NT);
    const int rem  = lin - band * 8 * NT;
    const int m0   = (band * 8 + (rem & 7)) * BM;
    const int n0   = (rem >> 3) * BN;

    const int KT = K / BK;

    // ldmatrix per-lane byte offsets (stage-relative, k-step invariant)
    const int l7 = lane & 7;
    unsigned offA[4], offB[4];
#pragma unroll
    for (int mt = 0; mt < 4; mt++) {
        const int rowa = wm + mt * 16 + l7 + 8 * ((lane >> 3) & 1);
        offA[mt] = rowa * ROW_B + (((lane >> 4) & 1) * 8) * 2;
    }
#pragma unroll
    for (int p = 0; p < 4; p++) {
        const int rowb = wn + p * 16 + l7 + 8 * ((lane >> 4) & 1);
        offB[p] = BM * ROW_B + rowb * ROW_B + (((lane >> 3) & 1) * 8) * 2;
    }

    float acc[4][8][4];
#pragma unroll
    for (int i = 0; i < 4; i++)
#pragma unroll
        for (int j = 0; j < 8; j++)
#pragma unroll
            for (int k = 0; k < 4; k++) acc[i][j][k] = 0.f;

    // fragment ping-pong buffers (kept primed across stages)
    unsigned af[2][4][4], bf[2][8][2];

    auto issue_stage = [&](int slot, int kt) {
        const unsigned abase = smem_u32 + slot * STAGE_BYTES;
        const unsigned bbase = abase + BM * ROW_B;
        const int k0 = kt * BK;
#pragma unroll
        for (int i = 0; i < 4; i++) {            // A: 1024 chunks
            const int idx = tid + i * 256;
            const int r = idx >> 3, c = idx & 7;
            cp16(abase + r * ROW_B + c * 16, A + (size_t)(m0 + r) * K + k0 + c * 8);
        }
#pragma unroll
        for (int i = 0; i < 8; i++) {            // B: 2048 chunks
            const int idx = tid + i * 256;
            const int r = idx >> 3, c = idx & 7;
            cp16(bbase + r * ROW_B + c * 16, BT + (size_t)(n0 + r) * K + k0 + c * 8);
        }
    };

    auto load_frags = [&](int buf, unsigned sbase, int ks) {
        const unsigned kadd = ks * 32;           // 16 halves
#pragma unroll
        for (int mt = 0; mt < 4; mt++)
            ldsm4(af[buf][mt][0], af[buf][mt][1], af[buf][mt][2], af[buf][mt][3],
                  sbase + offA[mt] + kadd);
#pragma unroll
        for (int p = 0; p < 4; p++)
            ldsm4(bf[buf][2 * p][0], bf[buf][2 * p][1],
                  bf[buf][2 * p + 1][0], bf[buf][2 * p + 1][1],
                  sbase + offB[p] + kadd);
    };

    auto mma_step = [&](int buf) {
#pragma unroll
        for (int mt = 0; mt < 4; mt++)
#pragma unroll
            for (int nt = 0; nt < 8; nt++) {
                asm volatile(
                    "mma.sync.aligned.m16n8k16.row.col.f32.f16.f16.f32 "
                    "{%0,%1,%2,%3},{%4,%5,%6,%7},{%8,%9},{%0,%1,%2,%3};"
                    : "+f"(acc[mt][nt][0]), "+f"(acc[mt][nt][1]),
                      "+f"(acc[mt][nt][2]), "+f"(acc[mt][nt][3])
                    : "r"(af[buf][mt][0]), "r"(af[buf][mt][1]),
                      "r"(af[buf][mt][2]), "r"(af[buf][mt][3]),
                      "r"(bf[buf][nt][0]), "r"(bf[buf][nt][1]));
            }
    };

    // prologue: stages 0,1 in flight; wait stage 0; prime fragment pipe
    issue_stage(0, 0);
    asm volatile("cp.async.commit_group;" ::: "memory");
    issue_stage(1, 1);
    asm volatile("cp.async.commit_group;" ::: "memory");
    asm volatile("cp.async.wait_group 1;" ::: "memory");
    __syncthreads();

    int buf = 0, slot = 0;
    load_frags(0, smem_u32, 0);                  // stage 0, ks 0

#pragma unroll 1
    for (int kt = 0; kt < KT; kt++) {
        const unsigned sbase = smem_u32 + slot * STAGE_BYTES;

        // issue stage kt+2 (slot kt+2 mod 3 = kt-1 mod 3: its last LDSM
        // happened before the previous barrier). Always commit (empty group
        // at tail keeps wait_group accounting exact).
        if (kt + 2 < KT) {
            int ns = slot + 2; if (ns >= NSTG) ns -= NSTG;
            issue_stage(ns, kt + 2);
        }
        asm volatile("cp.async.commit_group;" ::: "memory");

        // k-steps 0..2: prefetch next k-step, MMA current
#pragma unroll
        for (int ks = 0; ks < BK / 16 - 1; ks++) {
            load_frags(buf ^ 1, sbase, ks + 1);
            mma_step(buf);
            buf ^= 1;
        }

        // k-step 3: make next stage resident, prefetch ITS ks0, then MMA
        if (kt + 1 < KT) {
            asm volatile("cp.async.wait_group 1;" ::: "memory");
            __syncthreads();
            int ns = slot + 1; if (ns >= NSTG) ns -= NSTG;
            load_frags(buf ^ 1, smem_u32 + ns * STAGE_BYTES, 0);
        }
        mma_step(buf);
        buf ^= 1;

        if (++slot == NSTG) slot = 0;
    }

    // epilogue: thread owns rows wm+mt*16+g(+8), cols wn+nt*8+2t(+1)
#pragma unroll
    for (int mt = 0; mt < 4; mt++) {
#pragma unroll
        for (int nt = 0; nt < 8; nt++) {
            const int col = n0 + wn + nt * 8 + 2 * t;
#pragma unroll
            for (int h = 0; h < 2; h++) {
                const int row = m0 + wm + mt * 16 + g + h * 8;
                const size_t off = (size_t)row * Ntot + col;
                float vx = acc[mt][nt][h * 2 + 0];
                float vy = acc[mt][nt][h * 2 + 1];
                if (EPI == 0) {
                    __half2 o;
                    o.x = __float2half_rn(gelu_tanh(vx + bias[col]));
                    o.y = __float2half_rn(gelu_tanh(vy + bias[col + 1]));
                    *(__half2*)((__half*)Cv + off) = o;
                } else {
                    float2 o;
                    o.x = vx + resid[off]     + bias[col];
                    o.y = vy + resid[off + 1] + bias[col + 1];
                    *(float2*)((float*)Cv + off) = o;
                }
            }
        }
    }
}

// ---------------------------------------------------------------------------
// Launch
// ---------------------------------------------------------------------------
extern "C" void kernel_launch(void* const* d_in, const int* in_sizes, int n_in,
                              void* d_out, int out_size)
{
    const float* input     = (const float*)d_in[0];
    const float* residual  = (const float*)d_in[1];
    // d_in[2] = residual_norm: unused by the reference
    const float* attn_bias = (const float*)d_in[3];
    const float* attn_nw   = (const float*)d_in[4];
    const float* attn_nb   = (const float*)d_in[5];
    const float* inter_w   = (const float*)d_in[6];
    const float* inter_b   = (const float*)d_in[7];
    const float* output_w  = (const float*)d_in[8];
    const float* output_b  = (const float*)d_in[9];
    float* out = (float*)d_out;

    __half *ln_p, *inter_p, *w1t_p, *w2t_p;
    float *res_p;
    cudaGetSymbolAddress((void**)&ln_p, g_ln);
    cudaGetSymbolAddress((void**)&res_p, g_res);
    cudaGetSymbolAddress((void**)&inter_p, g_inter);
    cudaGetSymbolAddress((void**)&w1t_p, g_w1t);
    cudaGetSymbolAddress((void**)&w2t_p, g_w2t);

    cudaFuncSetAttribute(gemm_mma<0>, cudaFuncAttributeMaxDynamicSharedMemorySize, GEMM_SMEM);
    cudaFuncSetAttribute(gemm_mma<1>, cudaFuncAttributeMaxDynamicSharedMemorySize, GEMM_SMEM);

    // weight prep: transpose + fp16 round
    transpose_h<<<dim3(INT_DIM / 32, HID / 32), 256>>>(inter_w,  w1t_p, HID, INT_DIM);
    transpose_h<<<dim3(HID / 32, INT_DIM / 32), 256>>>(output_w, w2t_p, INT_DIM, HID);

    addln_kernel<<<MTOK, 256>>>(input, residual, attn_bias, attn_nw, attn_nb);

    // GEMM1: [8192,4096] x [4096,16384] -> g_inter (gelu, fp16)
    gemm_mma<0><<<(MTOK / BM) * (INT_DIM / BN), 256, GEMM_SMEM>>>(
        ln_p, w1t_p, inter_b, nullptr, inter_p, INT_DIM, HID, INT_DIM / BN);

    // GEMM2: [8192,16384] x [16384,4096] -> out (+res+bias, fp32)
    gemm_mma<1><<<(MTOK / BM) * (HID / BN), 256, GEMM_SMEM>>>(
        inter_p, w2t_p, output_b, res_p, out, HID, INT_DIM, HID / BN);
}